// round 2
// baseline (speedup 1.0000x reference)
#include <cuda_runtime.h>

#define SEQ 262144
#define HID 256
#define GRP 8

// Scratch: delta of input drive, dc_t = K*B*(u_{t+1}-u_t).  Padded so the
// double-buffer prefetch can read one group past the end harmlessly.
__device__ float4 g_dc[SEQ + GRP];

__device__ __forceinline__ float ex2f(float x) {
    float y; asm("ex2.approx.f32 %0, %1;" : "=f"(y) : "f"(x)); return y;
}
__device__ __forceinline__ float rcpf(float x) {
    float y; asm("rcp.approx.f32 %0, %1;" : "=f"(y) : "f"(x)); return y;
}

// ---------------------------------------------------------------------------
// Kernel 1: dc_t = K*(B (u_{t+1}-u_t)),  K = 2*log2(e).  (bA cancels.)
// ---------------------------------------------------------------------------
__global__ void prep_kernel(const float* __restrict__ u,
                            const float* __restrict__ B) {
    int t = blockIdx.x * blockDim.x + threadIdx.x;
    if (t >= SEQ) return;
    const float K = 2.8853900817779268f;
    int tn = (t + 1 < SEQ) ? t + 1 : t;   // last dc unused -> 0
    float d0 = u[tn] - u[t];
    float d1 = u[SEQ + tn] - u[SEQ + t];
    float d2 = u[2 * SEQ + tn] - u[2 * SEQ + t];
    float dc0 = K * fmaf(B[0], d0, fmaf(B[1], d1, B[2] * d2));
    float dc1 = K * fmaf(B[3], d0, fmaf(B[4], d1, B[5] * d2));
    float dc2 = K * fmaf(B[6], d0, fmaf(B[7], d1, B[8] * d2));
    g_dc[t] = make_float4(dc0, dc1, dc2, 0.f);
}

// ---------------------------------------------------------------------------
// Kernel 2: serial scan, single thread, iterating w = K*(A x + B u + bA):
//   T = tanh = 1 - 2/(1 + 2^w)          (ex2 + rcp, full accuracy)
//   x += dt*T                            (off critical path)
//   w  = (w + dc_t) + (K*dt*A)*T
// Membrane x_t written planar straight into d_out[3*SEQ ...], packed 4/STG.
// ---------------------------------------------------------------------------
__global__ void scan_kernel(const float* __restrict__ u,
                            const float* __restrict__ A,
                            const float* __restrict__ B,
                            const float* __restrict__ bA,
                            const float* __restrict__ dtp,
                            float* __restrict__ out) {
    if (threadIdx.x != 0 || blockIdx.x != 0) return;
    const float K = 2.8853900817779268f;
    const float dt = dtp[0];
    const float kd = K * dt;
    const float a00 = kd * A[0], a01 = kd * A[1], a02 = kd * A[2];
    const float a10 = kd * A[3], a11 = kd * A[4], a12 = kd * A[5];
    const float a20 = kd * A[6], a21 = kd * A[7], a22 = kd * A[8];

    // w_0 = K*(B u_0 + bA)   (x_0 = 0)
    float u0 = u[0], u1 = u[SEQ], u2 = u[2 * SEQ];
    float w0 = K * fmaf(B[0], u0, fmaf(B[1], u1, fmaf(B[2], u2, bA[0])));
    float w1 = K * fmaf(B[3], u0, fmaf(B[4], u1, fmaf(B[5], u2, bA[1])));
    float w2 = K * fmaf(B[6], u0, fmaf(B[7], u1, fmaf(B[8], u2, bA[2])));

    float x0 = 0.f, x1 = 0.f, x2 = 0.f;
    float* __restrict__ m0 = out + 3 * SEQ;
    float* __restrict__ m1 = out + 4 * SEQ;
    float* __restrict__ m2 = out + 5 * SEQ;

    float4 cur[GRP], nxt[GRP];
#pragma unroll
    for (int k = 0; k < GRP; k++) cur[k] = g_dc[k];

    float px0[4], px1[4], px2[4];

    for (int t = 0; t < SEQ; t += GRP) {
        // prefetch next group (pad makes the tail read safe)
#pragma unroll
        for (int k = 0; k < GRP; k++) nxt[k] = g_dc[t + GRP + k];

#pragma unroll
        for (int k = 0; k < GRP; k++) {
            float E0 = ex2f(w0), E1 = ex2f(w1), E2 = ex2f(w2);
            float T0 = fmaf(-2.f, rcpf(E0 + 1.f), 1.f);
            float T1 = fmaf(-2.f, rcpf(E1 + 1.f), 1.f);
            float T2 = fmaf(-2.f, rcpf(E2 + 1.f), 1.f);
            // off-critical: state update for output
            x0 = fmaf(dt, T0, x0);
            x1 = fmaf(dt, T1, x1);
            x2 = fmaf(dt, T2, x2);
            // off-critical while MUFUs run: s = w + dc
            float s0 = w0 + cur[k].x;
            float s1 = w1 + cur[k].y;
            float s2 = w2 + cur[k].z;
            // critical: w' = s + (K dt A) T
            w0 = fmaf(a00, T0, fmaf(a01, T1, fmaf(a02, T2, s0)));
            w1 = fmaf(a10, T0, fmaf(a11, T1, fmaf(a12, T2, s1)));
            w2 = fmaf(a20, T0, fmaf(a21, T1, fmaf(a22, T2, s2)));

            px0[k & 3] = x0; px1[k & 3] = x1; px2[k & 3] = x2;
            if ((k & 3) == 3) {
                int base = t + k - 3;
                *reinterpret_cast<float4*>(m0 + base) = make_float4(px0[0], px0[1], px0[2], px0[3]);
                *reinterpret_cast<float4*>(m1 + base) = make_float4(px1[0], px1[1], px1[2], px1[3]);
                *reinterpret_cast<float4*>(m2 + base) = make_float4(px2[0], px2[1], px2[2], px2[3]);
            }
        }
#pragma unroll
        for (int k = 0; k < GRP; k++) cur[k] = nxt[k];
    }
}

// ---------------------------------------------------------------------------
// Kernel 3: parallel MLP over timesteps, reading planar membrane from d_out.
// ---------------------------------------------------------------------------
__global__ void mlp_kernel(const float* __restrict__ W1,
                           const float* __restrict__ b1,
                           const float* __restrict__ W2,
                           const float* __restrict__ b2,
                           float* __restrict__ out) {
    __shared__ float sW1[3 * HID];
    __shared__ float sW2[3 * HID];
    __shared__ float sb1[HID];
    __shared__ float sb2[4];

    for (int i = threadIdx.x; i < 3 * HID; i += blockDim.x) {
        sW1[i] = W1[i];
        sW2[i] = W2[i];
    }
    for (int i = threadIdx.x; i < HID; i += blockDim.x) sb1[i] = b1[i];
    if (threadIdx.x < 3) sb2[threadIdx.x] = b2[threadIdx.x];
    __syncthreads();

    int tid = blockIdx.x * blockDim.x + threadIdx.x;
    int t = tid * 4;
    if (t >= SEQ) return;

    const float* __restrict__ m0 = out + 3 * SEQ;
    const float* __restrict__ m1 = out + 4 * SEQ;
    const float* __restrict__ m2 = out + 5 * SEQ;

    float4 v0 = *reinterpret_cast<const float4*>(m0 + t);
    float4 v1 = *reinterpret_cast<const float4*>(m1 + t);
    float4 v2 = *reinterpret_cast<const float4*>(m2 + t);
    float xs0[4] = {v0.x, v0.y, v0.z, v0.w};
    float xs1[4] = {v1.x, v1.y, v1.z, v1.w};
    float xs2[4] = {v2.x, v2.y, v2.z, v2.w};

    float acc0[4], acc1[4], acc2[4];
#pragma unroll
    for (int k = 0; k < 4; k++) {
        acc0[k] = sb2[0]; acc1[k] = sb2[1]; acc2[k] = sb2[2];
    }

#pragma unroll 4
    for (int j = 0; j < HID; j++) {
        float w10 = sW1[3 * j], w11 = sW1[3 * j + 1], w12 = sW1[3 * j + 2];
        float bj = sb1[j];
        float q0 = sW2[j], q1 = sW2[HID + j], q2 = sW2[2 * HID + j];
#pragma unroll
        for (int k = 0; k < 4; k++) {
            float h = fmaf(w10, xs0[k], fmaf(w11, xs1[k], fmaf(w12, xs2[k], bj)));
            h = fmaxf(h, 0.f);
            acc0[k] = fmaf(q0, h, acc0[k]);
            acc1[k] = fmaf(q1, h, acc1[k]);
            acc2[k] = fmaf(q2, h, acc2[k]);
        }
    }

    *reinterpret_cast<float4*>(out + 0 * SEQ + t) = make_float4(acc0[0], acc0[1], acc0[2], acc0[3]);
    *reinterpret_cast<float4*>(out + 1 * SEQ + t) = make_float4(acc1[0], acc1[1], acc1[2], acc1[3]);
    *reinterpret_cast<float4*>(out + 2 * SEQ + t) = make_float4(acc2[0], acc2[1], acc2[2], acc2[3]);
}

// ---------------------------------------------------------------------------
extern "C" void kernel_launch(void* const* d_in, const int* in_sizes, int n_in,
                              void* d_out, int out_size) {
    const float* u  = (const float*)d_in[0];
    const float* dt = (const float*)d_in[1];
    const float* A  = (const float*)d_in[2];
    const float* B  = (const float*)d_in[3];
    const float* bA = (const float*)d_in[4];
    const float* W1 = (const float*)d_in[5];
    const float* b1 = (const float*)d_in[6];
    const float* W2 = (const float*)d_in[7];
    const float* b2 = (const float*)d_in[8];
    float* out = (float*)d_out;

    prep_kernel<<<SEQ / 256, 256>>>(u, B);
    scan_kernel<<<1, 32>>>(u, A, B, bA, dt, out);
    mlp_kernel<<<SEQ / 4 / 128, 128>>>(W1, b1, W2, b2, out);
}

// round 3
// speedup vs baseline: 21.9595x; 21.9595x over previous
#include <cuda_runtime.h>

#define SEQ    262144
#define HID    256
#define CHUNKS 512
#define CLEN   512          // SEQ / CHUNKS

// Scratch (static — no allocs allowed)
__device__ float4 g_cT[SEQ];           // K*(B u_t + bA), interleaved [tw][chunk]
__device__ float4 g_xT[SEQ];           // membrane states, interleaved [tw][chunk]
__device__ float4 g_F[CHUNKS];         // chunk-end states from last sweep
__device__ float4 g_Jr[CHUNKS][3];     // chunk Jacobian rows (chord, from sweep 1)
__device__ float4 g_S[2][CHUNKS + 1];  // ping-pong chunk-start states

__device__ __forceinline__ float ex2f(float x) {
    float y; asm("ex2.approx.f32 %0, %1;" : "=f"(y) : "f"(x)); return y;
}
__device__ __forceinline__ float rcpf(float x) {
    float y; asm("rcp.approx.f32 %0, %1;" : "=f"(y) : "f"(x)); return y;
}

// ---------------------------------------------------------------------------
// Kernel 1: c_t = K*(B u_t + bA), K = 2*log2(e), stored interleaved.
// ---------------------------------------------------------------------------
__global__ void prep_kernel(const float* __restrict__ u,
                            const float* __restrict__ B,
                            const float* __restrict__ bA) {
    int t = blockIdx.x * blockDim.x + threadIdx.x;
    if (t >= SEQ) return;
    const float K = 2.8853900817779268f;
    float u0 = u[t], u1 = u[SEQ + t], u2 = u[2 * SEQ + t];
    float c0 = K * fmaf(B[0], u0, fmaf(B[1], u1, fmaf(B[2], u2, bA[0])));
    float c1 = K * fmaf(B[3], u0, fmaf(B[4], u1, fmaf(B[5], u2, bA[1])));
    float c2 = K * fmaf(B[6], u0, fmaf(B[7], u1, fmaf(B[8], u2, bA[2])));
    int ch = t / CLEN, tw = t % CLEN;
    g_cT[tw * CHUNKS + ch] = make_float4(c0, c1, c2, 0.f);
}

__global__ void init_kernel() {
    int i = threadIdx.x + blockIdx.x * blockDim.x;
    if (i <= CHUNKS) {
        g_S[0][i] = make_float4(0.f, 0.f, 0.f, 0.f);
        g_S[1][i] = make_float4(0.f, 0.f, 0.f, 0.f);
    }
}

// ---------------------------------------------------------------------------
// Kernel 2: parallel chunk sweep. One lane per chunk (pure SIMD).
//   mode 0: integrate state + 3x3 Jacobian (chord), write F and J
//   mode 1: integrate state only, write F
//   mode 2: integrate state only, store every x_t interleaved (final)
// tanh(z) = 1 - 2/(1 + 2^(K z)) via ex2+rcp (full accuracy).
// ---------------------------------------------------------------------------
__global__ void sweep_kernel(const float* __restrict__ A,
                             const float* __restrict__ dtp,
                             int mode, int src) {
    int ch = blockIdx.x * blockDim.x + threadIdx.x;
    if (ch >= CHUNKS) return;
    const float K = 2.8853900817779268f;
    const float dt = dtp[0];
    const float a00 = A[0], a01 = A[1], a02 = A[2];
    const float a10 = A[3], a11 = A[4], a12 = A[5];
    const float a20 = A[6], a21 = A[7], a22 = A[8];
    const float k00 = K * a00, k01 = K * a01, k02 = K * a02;
    const float k10 = K * a10, k11 = K * a11, k12 = K * a12;
    const float k20 = K * a20, k21 = K * a21, k22 = K * a22;

    float4 s = g_S[src][ch];
    float x0 = s.x, x1 = s.y, x2 = s.z;

    if (mode == 0) {
        float J00 = 1.f, J01 = 0.f, J02 = 0.f;
        float J10 = 0.f, J11 = 1.f, J12 = 0.f;
        float J20 = 0.f, J21 = 0.f, J22 = 1.f;
#pragma unroll 2
        for (int tw = 0; tw < CLEN; tw++) {
            float4 c = g_cT[tw * CHUNKS + ch];
            float w0 = fmaf(k00, x0, fmaf(k01, x1, fmaf(k02, x2, c.x)));
            float w1 = fmaf(k10, x0, fmaf(k11, x1, fmaf(k12, x2, c.y)));
            float w2 = fmaf(k20, x0, fmaf(k21, x1, fmaf(k22, x2, c.z)));
            float T0 = fmaf(-2.f, rcpf(ex2f(w0) + 1.f), 1.f);
            float T1 = fmaf(-2.f, rcpf(ex2f(w1) + 1.f), 1.f);
            float T2 = fmaf(-2.f, rcpf(ex2f(w2) + 1.f), 1.f);
            x0 = fmaf(dt, T0, x0);
            x1 = fmaf(dt, T1, x1);
            x2 = fmaf(dt, T2, x2);
            float d0 = dt * fmaf(-T0, T0, 1.f);
            float d1 = dt * fmaf(-T1, T1, 1.f);
            float d2 = dt * fmaf(-T2, T2, 1.f);
            // M = A*J ; J += diag(d)*M
            float m00 = fmaf(a00, J00, fmaf(a01, J10, a02 * J20));
            float m01 = fmaf(a00, J01, fmaf(a01, J11, a02 * J21));
            float m02 = fmaf(a00, J02, fmaf(a01, J12, a02 * J22));
            float m10 = fmaf(a10, J00, fmaf(a11, J10, a12 * J20));
            float m11 = fmaf(a10, J01, fmaf(a11, J11, a12 * J21));
            float m12 = fmaf(a10, J02, fmaf(a11, J12, a12 * J22));
            float m20 = fmaf(a20, J00, fmaf(a21, J10, a22 * J20));
            float m21 = fmaf(a20, J01, fmaf(a21, J11, a22 * J21));
            float m22 = fmaf(a20, J02, fmaf(a21, J12, a22 * J22));
            J00 = fmaf(d0, m00, J00); J01 = fmaf(d0, m01, J01); J02 = fmaf(d0, m02, J02);
            J10 = fmaf(d1, m10, J10); J11 = fmaf(d1, m11, J11); J12 = fmaf(d1, m12, J12);
            J20 = fmaf(d2, m20, J20); J21 = fmaf(d2, m21, J21); J22 = fmaf(d2, m22, J22);
        }
        g_F[ch] = make_float4(x0, x1, x2, 0.f);
        g_Jr[ch][0] = make_float4(J00, J01, J02, 0.f);
        g_Jr[ch][1] = make_float4(J10, J11, J12, 0.f);
        g_Jr[ch][2] = make_float4(J20, J21, J22, 0.f);
    } else if (mode == 1) {
#pragma unroll 4
        for (int tw = 0; tw < CLEN; tw++) {
            float4 c = g_cT[tw * CHUNKS + ch];
            float w0 = fmaf(k00, x0, fmaf(k01, x1, fmaf(k02, x2, c.x)));
            float w1 = fmaf(k10, x0, fmaf(k11, x1, fmaf(k12, x2, c.y)));
            float w2 = fmaf(k20, x0, fmaf(k21, x1, fmaf(k22, x2, c.z)));
            float T0 = fmaf(-2.f, rcpf(ex2f(w0) + 1.f), 1.f);
            float T1 = fmaf(-2.f, rcpf(ex2f(w1) + 1.f), 1.f);
            float T2 = fmaf(-2.f, rcpf(ex2f(w2) + 1.f), 1.f);
            x0 = fmaf(dt, T0, x0);
            x1 = fmaf(dt, T1, x1);
            x2 = fmaf(dt, T2, x2);
        }
        g_F[ch] = make_float4(x0, x1, x2, 0.f);
    } else {
#pragma unroll 4
        for (int tw = 0; tw < CLEN; tw++) {
            float4 c = g_cT[tw * CHUNKS + ch];
            float w0 = fmaf(k00, x0, fmaf(k01, x1, fmaf(k02, x2, c.x)));
            float w1 = fmaf(k10, x0, fmaf(k11, x1, fmaf(k12, x2, c.y)));
            float w2 = fmaf(k20, x0, fmaf(k21, x1, fmaf(k22, x2, c.z)));
            float T0 = fmaf(-2.f, rcpf(ex2f(w0) + 1.f), 1.f);
            float T1 = fmaf(-2.f, rcpf(ex2f(w1) + 1.f), 1.f);
            float T2 = fmaf(-2.f, rcpf(ex2f(w2) + 1.f), 1.f);
            x0 = fmaf(dt, T0, x0);
            x1 = fmaf(dt, T1, x1);
            x2 = fmaf(dt, T2, x2);
            g_xT[tw * CHUNKS + ch] = make_float4(x0, x1, x2, 0.f);
        }
    }
}

// ---------------------------------------------------------------------------
// Kernel 3: serial compose (tiny): S_new[c+1] = F[c] + J[c]*(S_new[c]-S_old[c])
// ---------------------------------------------------------------------------
__global__ void compose_kernel(int so, int sn) {
    if (threadIdx.x != 0 || blockIdx.x != 0) return;
    float n0 = 0.f, n1 = 0.f, n2 = 0.f;
    g_S[sn][0] = make_float4(0.f, 0.f, 0.f, 0.f);
    for (int c = 0; c < CHUNKS; c++) {
        float4 old = g_S[so][c];
        float4 F  = g_F[c];
        float4 r0 = g_Jr[c][0];
        float4 r1 = g_Jr[c][1];
        float4 r2 = g_Jr[c][2];
        float e0 = n0 - old.x, e1 = n1 - old.y, e2 = n2 - old.z;
        n0 = fmaf(r0.x, e0, fmaf(r0.y, e1, fmaf(r0.z, e2, F.x)));
        n1 = fmaf(r1.x, e0, fmaf(r1.y, e1, fmaf(r1.z, e2, F.y)));
        n2 = fmaf(r2.x, e0, fmaf(r2.y, e1, fmaf(r2.z, e2, F.z)));
        g_S[sn][c + 1] = make_float4(n0, n1, n2, 0.f);
    }
}

// ---------------------------------------------------------------------------
// Kernel 4: parallel MLP; reads interleaved states, writes planar out+membrane.
// ---------------------------------------------------------------------------
__global__ void mlp_kernel(const float* __restrict__ W1,
                           const float* __restrict__ b1,
                           const float* __restrict__ W2,
                           const float* __restrict__ b2,
                           float* __restrict__ out) {
    __shared__ float sW1[3 * HID];
    __shared__ float sW2[3 * HID];
    __shared__ float sb1[HID];
    __shared__ float sb2[4];

    for (int i = threadIdx.x; i < 3 * HID; i += blockDim.x) {
        sW1[i] = W1[i];
        sW2[i] = W2[i];
    }
    for (int i = threadIdx.x; i < HID; i += blockDim.x) sb1[i] = b1[i];
    if (threadIdx.x < 3) sb2[threadIdx.x] = b2[threadIdx.x];
    __syncthreads();

    int tid = blockIdx.x * blockDim.x + threadIdx.x;
    int t = tid * 4;
    if (t >= SEQ) return;
    int ch = t / CLEN, tw = t % CLEN;

    float xs0[4], xs1[4], xs2[4];
#pragma unroll
    for (int k = 0; k < 4; k++) {
        float4 v = g_xT[(tw + k) * CHUNKS + ch];
        xs0[k] = v.x; xs1[k] = v.y; xs2[k] = v.z;
    }

    float acc0[4], acc1[4], acc2[4];
#pragma unroll
    for (int k = 0; k < 4; k++) {
        acc0[k] = sb2[0]; acc1[k] = sb2[1]; acc2[k] = sb2[2];
    }

#pragma unroll 4
    for (int j = 0; j < HID; j++) {
        float w10 = sW1[3 * j], w11 = sW1[3 * j + 1], w12 = sW1[3 * j + 2];
        float bj = sb1[j];
        float q0 = sW2[j], q1 = sW2[HID + j], q2 = sW2[2 * HID + j];
#pragma unroll
        for (int k = 0; k < 4; k++) {
            float h = fmaf(w10, xs0[k], fmaf(w11, xs1[k], fmaf(w12, xs2[k], bj)));
            h = fmaxf(h, 0.f);
            acc0[k] = fmaf(q0, h, acc0[k]);
            acc1[k] = fmaf(q1, h, acc1[k]);
            acc2[k] = fmaf(q2, h, acc2[k]);
        }
    }

    float* mem = out + 3 * SEQ;
    *reinterpret_cast<float4*>(out + 0 * SEQ + t) = make_float4(acc0[0], acc0[1], acc0[2], acc0[3]);
    *reinterpret_cast<float4*>(out + 1 * SEQ + t) = make_float4(acc1[0], acc1[1], acc1[2], acc1[3]);
    *reinterpret_cast<float4*>(out + 2 * SEQ + t) = make_float4(acc2[0], acc2[1], acc2[2], acc2[3]);
    *reinterpret_cast<float4*>(mem + 0 * SEQ + t) = make_float4(xs0[0], xs0[1], xs0[2], xs0[3]);
    *reinterpret_cast<float4*>(mem + 1 * SEQ + t) = make_float4(xs1[0], xs1[1], xs1[2], xs1[3]);
    *reinterpret_cast<float4*>(mem + 2 * SEQ + t) = make_float4(xs2[0], xs2[1], xs2[2], xs2[3]);
}

// ---------------------------------------------------------------------------
extern "C" void kernel_launch(void* const* d_in, const int* in_sizes, int n_in,
                              void* d_out, int out_size) {
    const float* u  = (const float*)d_in[0];
    const float* dt = (const float*)d_in[1];
    const float* A  = (const float*)d_in[2];
    const float* B  = (const float*)d_in[3];
    const float* bA = (const float*)d_in[4];
    const float* W1 = (const float*)d_in[5];
    const float* b1 = (const float*)d_in[6];
    const float* W2 = (const float*)d_in[7];
    const float* b2 = (const float*)d_in[8];
    float* out = (float*)d_out;

    prep_kernel<<<SEQ / 256, 256>>>(u, B, bA);
    init_kernel<<<(CHUNKS + 64) / 64, 64>>>();

    // Iteration 1: full sweep (state + chord Jacobian) from zero guesses
    sweep_kernel<<<CHUNKS / 32, 32>>>(A, dt, 0, 0);
    compose_kernel<<<1, 32>>>(0, 1);
    // Iterations 2..8: state-only sweeps, Jacobians reused (chord Newton)
    for (int k = 2; k <= 8; k++) {
        int src = (k & 1) ? 0 : 1;          // k even -> src 1, k odd -> src 0
        int dst = src ^ 1;
        sweep_kernel<<<CHUNKS / 32, 32>>>(A, dt, 1, src);
        compose_kernel<<<1, 32>>>(src, dst);
    }
    // After 8 composes the converged starts are in g_S[0].
    sweep_kernel<<<CHUNKS / 32, 32>>>(A, dt, 2, 0);

    mlp_kernel<<<SEQ / 4 / 128, 128>>>(W1, b1, W2, b2, out);
}

// round 4
// speedup vs baseline: 78.1564x; 3.5591x over previous
#include <cuda_runtime.h>

#define SEQ    262144
#define HID    256
#define CHUNKS 1024
#define CLEN   256          // SEQ / CHUNKS

// Scratch (static — no allocs allowed)
__device__ float4 g_cT[SEQ];           // K*(B u_t + bA), interleaved [tw][chunk]
__device__ float4 g_xT[SEQ];           // membrane states, interleaved [tw][chunk]
__device__ float4 g_F[CHUNKS];         // chunk-end states from last sweep
__device__ float4 g_Jr[CHUNKS][3];     // chunk Jacobian rows (chord, from sweep 1)
__device__ float4 g_S[2][CHUNKS + 1];  // ping-pong chunk-start states

__device__ __forceinline__ float ex2f(float x) {
    float y; asm("ex2.approx.f32 %0, %1;" : "=f"(y) : "f"(x)); return y;
}
__device__ __forceinline__ float rcpf(float x) {
    float y; asm("rcp.approx.f32 %0, %1;" : "=f"(y) : "f"(x)); return y;
}

// ---------------------------------------------------------------------------
// Kernel 1: c_t = K*(B u_t + bA), K = 2*log2(e), stored interleaved.
// ---------------------------------------------------------------------------
__global__ void prep_kernel(const float* __restrict__ u,
                            const float* __restrict__ B,
                            const float* __restrict__ bA) {
    int t = blockIdx.x * blockDim.x + threadIdx.x;
    if (t >= SEQ) return;
    const float K = 2.8853900817779268f;
    float u0 = u[t], u1 = u[SEQ + t], u2 = u[2 * SEQ + t];
    float c0 = K * fmaf(B[0], u0, fmaf(B[1], u1, fmaf(B[2], u2, bA[0])));
    float c1 = K * fmaf(B[3], u0, fmaf(B[4], u1, fmaf(B[5], u2, bA[1])));
    float c2 = K * fmaf(B[6], u0, fmaf(B[7], u1, fmaf(B[8], u2, bA[2])));
    int ch = t / CLEN, tw = t % CLEN;
    g_cT[tw * CHUNKS + ch] = make_float4(c0, c1, c2, 0.f);
}

__global__ void init_kernel() {
    int i = threadIdx.x + blockIdx.x * blockDim.x;
    if (i <= CHUNKS) {
        g_S[0][i] = make_float4(0.f, 0.f, 0.f, 0.f);
        g_S[1][i] = make_float4(0.f, 0.f, 0.f, 0.f);
    }
}

// ---------------------------------------------------------------------------
// Kernel 2: parallel chunk sweep. One lane per chunk (pure SIMD).
//   mode 0: integrate state + 3x3 chord Jacobian, write F and J
//   mode 1: integrate state only, write F
//   mode 2: integrate state only, store every x_t interleaved (final)
// ---------------------------------------------------------------------------
__global__ void sweep_kernel(const float* __restrict__ A,
                             const float* __restrict__ dtp,
                             int mode, int src) {
    int ch = blockIdx.x * blockDim.x + threadIdx.x;
    if (ch >= CHUNKS) return;
    const float K = 2.8853900817779268f;
    const float dt = dtp[0];
    const float a00 = A[0], a01 = A[1], a02 = A[2];
    const float a10 = A[3], a11 = A[4], a12 = A[5];
    const float a20 = A[6], a21 = A[7], a22 = A[8];
    const float k00 = K * a00, k01 = K * a01, k02 = K * a02;
    const float k10 = K * a10, k11 = K * a11, k12 = K * a12;
    const float k20 = K * a20, k21 = K * a21, k22 = K * a22;

    float4 s = g_S[src][ch];
    float x0 = s.x, x1 = s.y, x2 = s.z;

    if (mode == 0) {
        float J00 = 1.f, J01 = 0.f, J02 = 0.f;
        float J10 = 0.f, J11 = 1.f, J12 = 0.f;
        float J20 = 0.f, J21 = 0.f, J22 = 1.f;
#pragma unroll 2
        for (int tw = 0; tw < CLEN; tw++) {
            float4 c = g_cT[tw * CHUNKS + ch];
            float w0 = fmaf(k00, x0, fmaf(k01, x1, fmaf(k02, x2, c.x)));
            float w1 = fmaf(k10, x0, fmaf(k11, x1, fmaf(k12, x2, c.y)));
            float w2 = fmaf(k20, x0, fmaf(k21, x1, fmaf(k22, x2, c.z)));
            float T0 = fmaf(-2.f, rcpf(ex2f(w0) + 1.f), 1.f);
            float T1 = fmaf(-2.f, rcpf(ex2f(w1) + 1.f), 1.f);
            float T2 = fmaf(-2.f, rcpf(ex2f(w2) + 1.f), 1.f);
            x0 = fmaf(dt, T0, x0);
            x1 = fmaf(dt, T1, x1);
            x2 = fmaf(dt, T2, x2);
            float d0 = dt * fmaf(-T0, T0, 1.f);
            float d1 = dt * fmaf(-T1, T1, 1.f);
            float d2 = dt * fmaf(-T2, T2, 1.f);
            float m00 = fmaf(a00, J00, fmaf(a01, J10, a02 * J20));
            float m01 = fmaf(a00, J01, fmaf(a01, J11, a02 * J21));
            float m02 = fmaf(a00, J02, fmaf(a01, J12, a02 * J22));
            float m10 = fmaf(a10, J00, fmaf(a11, J10, a12 * J20));
            float m11 = fmaf(a10, J01, fmaf(a11, J11, a12 * J21));
            float m12 = fmaf(a10, J02, fmaf(a11, J12, a12 * J22));
            float m20 = fmaf(a20, J00, fmaf(a21, J10, a22 * J20));
            float m21 = fmaf(a20, J01, fmaf(a21, J11, a22 * J21));
            float m22 = fmaf(a20, J02, fmaf(a21, J12, a22 * J22));
            J00 = fmaf(d0, m00, J00); J01 = fmaf(d0, m01, J01); J02 = fmaf(d0, m02, J02);
            J10 = fmaf(d1, m10, J10); J11 = fmaf(d1, m11, J11); J12 = fmaf(d1, m12, J12);
            J20 = fmaf(d2, m20, J20); J21 = fmaf(d2, m21, J21); J22 = fmaf(d2, m22, J22);
        }
        g_F[ch] = make_float4(x0, x1, x2, 0.f);
        g_Jr[ch][0] = make_float4(J00, J01, J02, 0.f);
        g_Jr[ch][1] = make_float4(J10, J11, J12, 0.f);
        g_Jr[ch][2] = make_float4(J20, J21, J22, 0.f);
    } else if (mode == 1) {
#pragma unroll 8
        for (int tw = 0; tw < CLEN; tw++) {
            float4 c = g_cT[tw * CHUNKS + ch];
            float w0 = fmaf(k00, x0, fmaf(k01, x1, fmaf(k02, x2, c.x)));
            float w1 = fmaf(k10, x0, fmaf(k11, x1, fmaf(k12, x2, c.y)));
            float w2 = fmaf(k20, x0, fmaf(k21, x1, fmaf(k22, x2, c.z)));
            float T0 = fmaf(-2.f, rcpf(ex2f(w0) + 1.f), 1.f);
            float T1 = fmaf(-2.f, rcpf(ex2f(w1) + 1.f), 1.f);
            float T2 = fmaf(-2.f, rcpf(ex2f(w2) + 1.f), 1.f);
            x0 = fmaf(dt, T0, x0);
            x1 = fmaf(dt, T1, x1);
            x2 = fmaf(dt, T2, x2);
        }
        g_F[ch] = make_float4(x0, x1, x2, 0.f);
    } else {
#pragma unroll 8
        for (int tw = 0; tw < CLEN; tw++) {
            float4 c = g_cT[tw * CHUNKS + ch];
            float w0 = fmaf(k00, x0, fmaf(k01, x1, fmaf(k02, x2, c.x)));
            float w1 = fmaf(k10, x0, fmaf(k11, x1, fmaf(k12, x2, c.y)));
            float w2 = fmaf(k20, x0, fmaf(k21, x1, fmaf(k22, x2, c.z)));
            float T0 = fmaf(-2.f, rcpf(ex2f(w0) + 1.f), 1.f);
            float T1 = fmaf(-2.f, rcpf(ex2f(w1) + 1.f), 1.f);
            float T2 = fmaf(-2.f, rcpf(ex2f(w2) + 1.f), 1.f);
            x0 = fmaf(dt, T0, x0);
            x1 = fmaf(dt, T1, x1);
            x2 = fmaf(dt, T2, x2);
            g_xT[tw * CHUNKS + ch] = make_float4(x0, x1, x2, 0.f);
        }
    }
}

// ---------------------------------------------------------------------------
// Kernel 3: PARALLEL compose via Hillis-Steele inclusive scan over affine
// maps f_c(x) = J_c x + v_c, v_c = F_c - J_c*S_old_c.
// n_{c+1} = (f_c ∘ ... ∘ f_0)(0) = v-component of inclusive prefix.
// One block of CHUNKS threads; smem planes [12][CHUNKS] (conflict-free).
// ---------------------------------------------------------------------------
__global__ void compose_scan_kernel(int so, int sn) {
    __shared__ float sP[12][CHUNKS];   // 0..8: M row-major, 9..11: v
    int t = threadIdx.x;

    float4 r0 = g_Jr[t][0], r1 = g_Jr[t][1], r2 = g_Jr[t][2];
    float4 old = g_S[so][t];
    float4 F = g_F[t];

    float M[9] = {r0.x, r0.y, r0.z, r1.x, r1.y, r1.z, r2.x, r2.y, r2.z};
    float v0 = F.x - (fmaf(r0.x, old.x, fmaf(r0.y, old.y, r0.z * old.z)));
    float v1 = F.y - (fmaf(r1.x, old.x, fmaf(r1.y, old.y, r1.z * old.z)));
    float v2 = F.z - (fmaf(r2.x, old.x, fmaf(r2.y, old.y, r2.z * old.z)));

#pragma unroll
    for (int k = 0; k < 9; k++) sP[k][t] = M[k];
    sP[9][t] = v0; sP[10][t] = v1; sP[11][t] = v2;
    __syncthreads();

    for (int off = 1; off < CHUNKS; off <<= 1) {
        float pM[9], pv0, pv1, pv2;
        bool act = (t >= off);
        if (act) {
#pragma unroll
            for (int k = 0; k < 9; k++) pM[k] = sP[k][t - off];
            pv0 = sP[9][t - off]; pv1 = sP[10][t - off]; pv2 = sP[11][t - off];
        }
        __syncthreads();
        if (act) {
            // new = cur ∘ prev :  M' = M·pM,  v' = M·pv + v
            float n0 = fmaf(M[0], pM[0], fmaf(M[1], pM[3], M[2] * pM[6]));
            float n1 = fmaf(M[0], pM[1], fmaf(M[1], pM[4], M[2] * pM[7]));
            float n2 = fmaf(M[0], pM[2], fmaf(M[1], pM[5], M[2] * pM[8]));
            float n3 = fmaf(M[3], pM[0], fmaf(M[4], pM[3], M[5] * pM[6]));
            float n4 = fmaf(M[3], pM[1], fmaf(M[4], pM[4], M[5] * pM[7]));
            float n5 = fmaf(M[3], pM[2], fmaf(M[4], pM[5], M[5] * pM[8]));
            float n6 = fmaf(M[6], pM[0], fmaf(M[7], pM[3], M[8] * pM[6]));
            float n7 = fmaf(M[6], pM[1], fmaf(M[7], pM[4], M[8] * pM[7]));
            float n8 = fmaf(M[6], pM[2], fmaf(M[7], pM[5], M[8] * pM[8]));
            float w0 = fmaf(M[0], pv0, fmaf(M[1], pv1, fmaf(M[2], pv2, v0)));
            float w1 = fmaf(M[3], pv0, fmaf(M[4], pv1, fmaf(M[5], pv2, v1)));
            float w2 = fmaf(M[6], pv0, fmaf(M[7], pv1, fmaf(M[8], pv2, v2)));
            M[0] = n0; M[1] = n1; M[2] = n2;
            M[3] = n3; M[4] = n4; M[5] = n5;
            M[6] = n6; M[7] = n7; M[8] = n8;
            v0 = w0; v1 = w1; v2 = w2;
#pragma unroll
            for (int k = 0; k < 9; k++) sP[k][t] = M[k];
            sP[9][t] = v0; sP[10][t] = v1; sP[11][t] = v2;
        }
        __syncthreads();
    }

    if (t == 0) g_S[sn][0] = make_float4(0.f, 0.f, 0.f, 0.f);
    g_S[sn][t + 1] = make_float4(v0, v1, v2, 0.f);
}

// ---------------------------------------------------------------------------
// Kernel 4: parallel MLP; reads interleaved states, writes planar out+membrane.
// ---------------------------------------------------------------------------
__global__ void mlp_kernel(const float* __restrict__ W1,
                           const float* __restrict__ b1,
                           const float* __restrict__ W2,
                           const float* __restrict__ b2,
                           float* __restrict__ out) {
    __shared__ float sW1[3 * HID];
    __shared__ float sW2[3 * HID];
    __shared__ float sb1[HID];
    __shared__ float sb2[4];

    for (int i = threadIdx.x; i < 3 * HID; i += blockDim.x) {
        sW1[i] = W1[i];
        sW2[i] = W2[i];
    }
    for (int i = threadIdx.x; i < HID; i += blockDim.x) sb1[i] = b1[i];
    if (threadIdx.x < 3) sb2[threadIdx.x] = b2[threadIdx.x];
    __syncthreads();

    int tid = blockIdx.x * blockDim.x + threadIdx.x;
    int t = tid * 4;
    if (t >= SEQ) return;
    int ch = t / CLEN, tw = t % CLEN;

    float xs0[4], xs1[4], xs2[4];
#pragma unroll
    for (int k = 0; k < 4; k++) {
        float4 v = g_xT[(tw + k) * CHUNKS + ch];
        xs0[k] = v.x; xs1[k] = v.y; xs2[k] = v.z;
    }

    float acc0[4], acc1[4], acc2[4];
#pragma unroll
    for (int k = 0; k < 4; k++) {
        acc0[k] = sb2[0]; acc1[k] = sb2[1]; acc2[k] = sb2[2];
    }

#pragma unroll 4
    for (int j = 0; j < HID; j++) {
        float w10 = sW1[3 * j], w11 = sW1[3 * j + 1], w12 = sW1[3 * j + 2];
        float bj = sb1[j];
        float q0 = sW2[j], q1 = sW2[HID + j], q2 = sW2[2 * HID + j];
#pragma unroll
        for (int k = 0; k < 4; k++) {
            float h = fmaf(w10, xs0[k], fmaf(w11, xs1[k], fmaf(w12, xs2[k], bj)));
            h = fmaxf(h, 0.f);
            acc0[k] = fmaf(q0, h, acc0[k]);
            acc1[k] = fmaf(q1, h, acc1[k]);
            acc2[k] = fmaf(q2, h, acc2[k]);
        }
    }

    float* mem = out + 3 * SEQ;
    *reinterpret_cast<float4*>(out + 0 * SEQ + t) = make_float4(acc0[0], acc0[1], acc0[2], acc0[3]);
    *reinterpret_cast<float4*>(out + 1 * SEQ + t) = make_float4(acc1[0], acc1[1], acc1[2], acc1[3]);
    *reinterpret_cast<float4*>(out + 2 * SEQ + t) = make_float4(acc2[0], acc2[1], acc2[2], acc2[3]);
    *reinterpret_cast<float4*>(mem + 0 * SEQ + t) = make_float4(xs0[0], xs0[1], xs0[2], xs0[3]);
    *reinterpret_cast<float4*>(mem + 1 * SEQ + t) = make_float4(xs1[0], xs1[1], xs1[2], xs1[3]);
    *reinterpret_cast<float4*>(mem + 2 * SEQ + t) = make_float4(xs2[0], xs2[1], xs2[2], xs2[3]);
}

// ---------------------------------------------------------------------------
extern "C" void kernel_launch(void* const* d_in, const int* in_sizes, int n_in,
                              void* d_out, int out_size) {
    const float* u  = (const float*)d_in[0];
    const float* dt = (const float*)d_in[1];
    const float* A  = (const float*)d_in[2];
    const float* B  = (const float*)d_in[3];
    const float* bA = (const float*)d_in[4];
    const float* W1 = (const float*)d_in[5];
    const float* b1 = (const float*)d_in[6];
    const float* W2 = (const float*)d_in[7];
    const float* b2 = (const float*)d_in[8];
    float* out = (float*)d_out;

    prep_kernel<<<SEQ / 256, 256>>>(u, B, bA);
    init_kernel<<<(CHUNKS + 64) / 64, 64>>>();

    // Iteration 1: full sweep (state + chord Jacobian) from zero guesses
    sweep_kernel<<<CHUNKS / 64, 64>>>(A, dt, 0, 0);
    compose_scan_kernel<<<1, CHUNKS>>>(0, 1);
    // Iterations 2..8: state-only sweeps, Jacobians reused (chord Newton)
    int cur = 1;
    for (int k = 2; k <= 8; k++) {
        sweep_kernel<<<CHUNKS / 64, 64>>>(A, dt, 1, cur);
        compose_scan_kernel<<<1, CHUNKS>>>(cur, cur ^ 1);
        cur ^= 1;
    }
    // Final: store all states with converged chunk starts
    sweep_kernel<<<CHUNKS / 64, 64>>>(A, dt, 2, cur);

    mlp_kernel<<<SEQ / 4 / 128, 128>>>(W1, b1, W2, b2, out);
}

// round 7
// speedup vs baseline: 129.5959x; 1.6582x over previous
#include <cuda_runtime.h>

#define SEQ    262144
#define HID    256
#define CHUNKS 4096
#define CLEN   64           // SEQ / CHUNKS
#define SCANT  1024         // threads in compose scan block
#define GPT    4            // chunks per scan thread = CHUNKS/SCANT

// Scratch (static — no allocs allowed)
__device__ float4 g_cT[SEQ];           // K*(B u_t + bA), interleaved [tw][chunk]
__device__ float4 g_xT[SEQ];           // membrane states, interleaved [tw][chunk]
__device__ float4 g_F[CHUNKS];         // chunk-end states from last sweep
__device__ float4 g_Jr[CHUNKS][3];     // chunk Jacobian rows (refreshed every sweep)
__device__ float4 g_S[2][CHUNKS + 1];  // ping-pong chunk-start states

__device__ __forceinline__ float ex2f(float x) {
    float y; asm("ex2.approx.f32 %0, %1;" : "=f"(y) : "f"(x)); return y;
}
__device__ __forceinline__ float rcpf(float x) {
    float y; asm("rcp.approx.f32 %0, %1;" : "=f"(y) : "f"(x)); return y;
}

// Affine map f(x) = M x + v, stored as 3 rows; row i = (Mi0, Mi1, Mi2, vi)
struct Aff { float4 r0, r1, r2; };

// out = A ∘ B  (apply B first):  M' = A.M * B.M,  v' = A.M * B.v + A.v
__device__ __forceinline__ Aff comp(const Aff& A, const Aff& B) {
    Aff o;
    o.r0.x = fmaf(A.r0.x, B.r0.x, fmaf(A.r0.y, B.r1.x, A.r0.z * B.r2.x));
    o.r0.y = fmaf(A.r0.x, B.r0.y, fmaf(A.r0.y, B.r1.y, A.r0.z * B.r2.y));
    o.r0.z = fmaf(A.r0.x, B.r0.z, fmaf(A.r0.y, B.r1.z, A.r0.z * B.r2.z));
    o.r0.w = fmaf(A.r0.x, B.r0.w, fmaf(A.r0.y, B.r1.w, fmaf(A.r0.z, B.r2.w, A.r0.w)));
    o.r1.x = fmaf(A.r1.x, B.r0.x, fmaf(A.r1.y, B.r1.x, A.r1.z * B.r2.x));
    o.r1.y = fmaf(A.r1.x, B.r0.y, fmaf(A.r1.y, B.r1.y, A.r1.z * B.r2.y));
    o.r1.z = fmaf(A.r1.x, B.r0.z, fmaf(A.r1.y, B.r1.z, A.r1.z * B.r2.z));
    o.r1.w = fmaf(A.r1.x, B.r0.w, fmaf(A.r1.y, B.r1.w, fmaf(A.r1.z, B.r2.w, A.r1.w)));
    o.r2.x = fmaf(A.r2.x, B.r0.x, fmaf(A.r2.y, B.r1.x, A.r2.z * B.r2.x));
    o.r2.y = fmaf(A.r2.x, B.r0.y, fmaf(A.r2.y, B.r1.y, A.r2.z * B.r2.y));
    o.r2.z = fmaf(A.r2.x, B.r0.z, fmaf(A.r2.y, B.r1.z, A.r2.z * B.r2.z));
    o.r2.w = fmaf(A.r2.x, B.r0.w, fmaf(A.r2.y, B.r1.w, fmaf(A.r2.z, B.r2.w, A.r2.w)));
    return o;
}

// f_c with v_c = F_c - J_c * S_old_c
__device__ __forceinline__ Aff load_f(int c, int so) {
    float4 j0 = g_Jr[c][0], j1 = g_Jr[c][1], j2 = g_Jr[c][2];
    float4 S = g_S[so][c];
    float4 F = g_F[c];
    Aff f;
    f.r0 = make_float4(j0.x, j0.y, j0.z,
                       F.x - fmaf(j0.x, S.x, fmaf(j0.y, S.y, j0.z * S.z)));
    f.r1 = make_float4(j1.x, j1.y, j1.z,
                       F.y - fmaf(j1.x, S.x, fmaf(j1.y, S.y, j1.z * S.z)));
    f.r2 = make_float4(j2.x, j2.y, j2.z,
                       F.z - fmaf(j2.x, S.x, fmaf(j2.y, S.y, j2.z * S.z)));
    return f;
}

// ---------------------------------------------------------------------------
// Kernel 1: c_t = K*(B u_t + bA), K = 2*log2(e), stored interleaved.
// ---------------------------------------------------------------------------
__global__ void prep_kernel(const float* __restrict__ u,
                            const float* __restrict__ B,
                            const float* __restrict__ bA) {
    int t = blockIdx.x * blockDim.x + threadIdx.x;
    if (t >= SEQ) return;
    const float K = 2.8853900817779268f;
    float u0 = u[t], u1 = u[SEQ + t], u2 = u[2 * SEQ + t];
    float c0 = K * fmaf(B[0], u0, fmaf(B[1], u1, fmaf(B[2], u2, bA[0])));
    float c1 = K * fmaf(B[3], u0, fmaf(B[4], u1, fmaf(B[5], u2, bA[1])));
    float c2 = K * fmaf(B[6], u0, fmaf(B[7], u1, fmaf(B[8], u2, bA[2])));
    int ch = t / CLEN, tw = t % CLEN;
    g_cT[tw * CHUNKS + ch] = make_float4(c0, c1, c2, 0.f);
}

__global__ void init_kernel() {
    int i = threadIdx.x + blockIdx.x * blockDim.x;
    if (i <= CHUNKS) {
        g_S[0][i] = make_float4(0.f, 0.f, 0.f, 0.f);
        g_S[1][i] = make_float4(0.f, 0.f, 0.f, 0.f);
    }
}

// ---------------------------------------------------------------------------
// Kernel 2: parallel chunk sweep. One lane per chunk (pure SIMD).
//   mode 0: state + 3x3 Jacobian (fresh every sweep -> full Newton) -> F, J
//   mode 2: state only, store every x_t (final)
// ---------------------------------------------------------------------------
__global__ void sweep_kernel(const float* __restrict__ A,
                             const float* __restrict__ dtp,
                             int mode, int src) {
    int ch = blockIdx.x * blockDim.x + threadIdx.x;
    if (ch >= CHUNKS) return;
    const float K = 2.8853900817779268f;
    const float dt = dtp[0];
    const float a00 = A[0], a01 = A[1], a02 = A[2];
    const float a10 = A[3], a11 = A[4], a12 = A[5];
    const float a20 = A[6], a21 = A[7], a22 = A[8];
    const float k00 = K * a00, k01 = K * a01, k02 = K * a02;
    const float k10 = K * a10, k11 = K * a11, k12 = K * a12;
    const float k20 = K * a20, k21 = K * a21, k22 = K * a22;

    float4 s = g_S[src][ch];
    float x0 = s.x, x1 = s.y, x2 = s.z;

    if (mode == 0) {
        float J00 = 1.f, J01 = 0.f, J02 = 0.f;
        float J10 = 0.f, J11 = 1.f, J12 = 0.f;
        float J20 = 0.f, J21 = 0.f, J22 = 1.f;
#pragma unroll 4
        for (int tw = 0; tw < CLEN; tw++) {
            float4 c = g_cT[tw * CHUNKS + ch];
            float w0 = fmaf(k00, x0, fmaf(k01, x1, fmaf(k02, x2, c.x)));
            float w1 = fmaf(k10, x0, fmaf(k11, x1, fmaf(k12, x2, c.y)));
            float w2 = fmaf(k20, x0, fmaf(k21, x1, fmaf(k22, x2, c.z)));
            float T0 = fmaf(-2.f, rcpf(ex2f(w0) + 1.f), 1.f);
            float T1 = fmaf(-2.f, rcpf(ex2f(w1) + 1.f), 1.f);
            float T2 = fmaf(-2.f, rcpf(ex2f(w2) + 1.f), 1.f);
            x0 = fmaf(dt, T0, x0);
            x1 = fmaf(dt, T1, x1);
            x2 = fmaf(dt, T2, x2);
            float d0 = dt * fmaf(-T0, T0, 1.f);
            float d1 = dt * fmaf(-T1, T1, 1.f);
            float d2 = dt * fmaf(-T2, T2, 1.f);
            float m00 = fmaf(a00, J00, fmaf(a01, J10, a02 * J20));
            float m01 = fmaf(a00, J01, fmaf(a01, J11, a02 * J21));
            float m02 = fmaf(a00, J02, fmaf(a01, J12, a02 * J22));
            float m10 = fmaf(a10, J00, fmaf(a11, J10, a12 * J20));
            float m11 = fmaf(a10, J01, fmaf(a11, J11, a12 * J21));
            float m12 = fmaf(a10, J02, fmaf(a11, J12, a12 * J22));
            float m20 = fmaf(a20, J00, fmaf(a21, J10, a22 * J20));
            float m21 = fmaf(a20, J01, fmaf(a21, J11, a22 * J21));
            float m22 = fmaf(a20, J02, fmaf(a21, J12, a22 * J22));
            J00 = fmaf(d0, m00, J00); J01 = fmaf(d0, m01, J01); J02 = fmaf(d0, m02, J02);
            J10 = fmaf(d1, m10, J10); J11 = fmaf(d1, m11, J11); J12 = fmaf(d1, m12, J12);
            J20 = fmaf(d2, m20, J20); J21 = fmaf(d2, m21, J21); J22 = fmaf(d2, m22, J22);
        }
        g_F[ch] = make_float4(x0, x1, x2, 0.f);
        g_Jr[ch][0] = make_float4(J00, J01, J02, 0.f);
        g_Jr[ch][1] = make_float4(J10, J11, J12, 0.f);
        g_Jr[ch][2] = make_float4(J20, J21, J22, 0.f);
    } else {
#pragma unroll 8
        for (int tw = 0; tw < CLEN; tw++) {
            float4 c = g_cT[tw * CHUNKS + ch];
            float w0 = fmaf(k00, x0, fmaf(k01, x1, fmaf(k02, x2, c.x)));
            float w1 = fmaf(k10, x0, fmaf(k11, x1, fmaf(k12, x2, c.y)));
            float w2 = fmaf(k20, x0, fmaf(k21, x1, fmaf(k22, x2, c.z)));
            float T0 = fmaf(-2.f, rcpf(ex2f(w0) + 1.f), 1.f);
            float T1 = fmaf(-2.f, rcpf(ex2f(w1) + 1.f), 1.f);
            float T2 = fmaf(-2.f, rcpf(ex2f(w2) + 1.f), 1.f);
            x0 = fmaf(dt, T0, x0);
            x1 = fmaf(dt, T1, x1);
            x2 = fmaf(dt, T2, x2);
            g_xT[tw * CHUNKS + ch] = make_float4(x0, x1, x2, 0.f);
        }
    }
}

// ---------------------------------------------------------------------------
// Kernel 3: compose via group pre-compose (GPT chunks/thread) + Hillis-Steele
// scan over SCANT group maps (float4-packed smem) + vector walk for starts.
// n_{c+1} = f_c(n_c),  f_c(x) = J_c x + (F_c - J_c S_old_c),  n_0 = 0.
// ---------------------------------------------------------------------------
__global__ void compose_scan_kernel(int so, int sn) {
    __shared__ float4 s0[SCANT], s1[SCANT], s2[SCANT];
    int t = threadIdx.x;
    int c0 = t * GPT;

    // group map G = f_{c0+3} ∘ f_{c0+2} ∘ f_{c0+1} ∘ f_{c0}
    Aff G = load_f(c0, so);
#pragma unroll
    for (int j = 1; j < GPT; j++) G = comp(load_f(c0 + j, so), G);

    s0[t] = G.r0; s1[t] = G.r1; s2[t] = G.r2;
    __syncthreads();

    for (int off = 1; off < SCANT; off <<= 1) {
        Aff P;
        bool act = (t >= off);
        if (act) { P.r0 = s0[t - off]; P.r1 = s1[t - off]; P.r2 = s2[t - off]; }
        __syncthreads();
        if (act) {
            G = comp(G, P);
            s0[t] = G.r0; s1[t] = G.r1; s2[t] = G.r2;
        }
        __syncthreads();
    }

    // exclusive prefix applied to 0: start of chunk c0
    float e0 = 0.f, e1 = 0.f, e2 = 0.f;
    if (t > 0) { e0 = s0[t - 1].w; e1 = s1[t - 1].w; e2 = s2[t - 1].w; }

    // walk the GPT chunk starts by vector application
#pragma unroll
    for (int j = 0; j < GPT; j++) {
        g_S[sn][c0 + j] = make_float4(e0, e1, e2, 0.f);
        Aff f = load_f(c0 + j, so);
        float y0 = fmaf(f.r0.x, e0, fmaf(f.r0.y, e1, fmaf(f.r0.z, e2, f.r0.w)));
        float y1 = fmaf(f.r1.x, e0, fmaf(f.r1.y, e1, fmaf(f.r1.z, e2, f.r1.w)));
        float y2 = fmaf(f.r2.x, e0, fmaf(f.r2.y, e1, fmaf(f.r2.z, e2, f.r2.w)));
        e0 = y0; e1 = y1; e2 = y2;
    }
}

// ---------------------------------------------------------------------------
// Kernel 4: parallel MLP; reads interleaved states, writes planar out+membrane.
// ---------------------------------------------------------------------------
__global__ void mlp_kernel(const float* __restrict__ W1,
                           const float* __restrict__ b1,
                           const float* __restrict__ W2,
                           const float* __restrict__ b2,
                           float* __restrict__ out) {
    __shared__ float sW1[3 * HID];
    __shared__ float sW2[3 * HID];
    __shared__ float sb1[HID];
    __shared__ float sb2[4];

    for (int i = threadIdx.x; i < 3 * HID; i += blockDim.x) {
        sW1[i] = W1[i];
        sW2[i] = W2[i];
    }
    for (int i = threadIdx.x; i < HID; i += blockDim.x) sb1[i] = b1[i];
    if (threadIdx.x < 3) sb2[threadIdx.x] = b2[threadIdx.x];
    __syncthreads();

    int tid = blockIdx.x * blockDim.x + threadIdx.x;
    int t = tid * 4;
    if (t >= SEQ) return;
    int ch = t / CLEN, tw = t % CLEN;

    float xs0[4], xs1[4], xs2[4];
#pragma unroll
    for (int k = 0; k < 4; k++) {
        float4 v = g_xT[(tw + k) * CHUNKS + ch];
        xs0[k] = v.x; xs1[k] = v.y; xs2[k] = v.z;
    }

    float acc0[4], acc1[4], acc2[4];
#pragma unroll
    for (int k = 0; k < 4; k++) {
        acc0[k] = sb2[0]; acc1[k] = sb2[1]; acc2[k] = sb2[2];
    }

#pragma unroll 4
    for (int j = 0; j < HID; j++) {
        float w10 = sW1[3 * j], w11 = sW1[3 * j + 1], w12 = sW1[3 * j + 2];
        float bj = sb1[j];
        float q0 = sW2[j], q1 = sW2[HID + j], q2 = sW2[2 * HID + j];
#pragma unroll
        for (int k = 0; k < 4; k++) {
            float h = fmaf(w10, xs0[k], fmaf(w11, xs1[k], fmaf(w12, xs2[k], bj)));
            h = fmaxf(h, 0.f);
            acc0[k] = fmaf(q0, h, acc0[k]);
            acc1[k] = fmaf(q1, h, acc1[k]);
            acc2[k] = fmaf(q2, h, acc2[k]);
        }
    }

    float* mem = out + 3 * SEQ;
    *reinterpret_cast<float4*>(out + 0 * SEQ + t) = make_float4(acc0[0], acc0[1], acc0[2], acc0[3]);
    *reinterpret_cast<float4*>(out + 1 * SEQ + t) = make_float4(acc1[0], acc1[1], acc1[2], acc1[3]);
    *reinterpret_cast<float4*>(out + 2 * SEQ + t) = make_float4(acc2[0], acc2[1], acc2[2], acc2[3]);
    *reinterpret_cast<float4*>(mem + 0 * SEQ + t) = make_float4(xs0[0], xs0[1], xs0[2], xs0[3]);
    *reinterpret_cast<float4*>(mem + 1 * SEQ + t) = make_float4(xs1[0], xs1[1], xs1[2], xs1[3]);
    *reinterpret_cast<float4*>(mem + 2 * SEQ + t) = make_float4(xs2[0], xs2[1], xs2[2], xs2[3]);
}

// ---------------------------------------------------------------------------
extern "C" void kernel_launch(void* const* d_in, const int* in_sizes, int n_in,
                              void* d_out, int out_size) {
    const float* u  = (const float*)d_in[0];
    const float* dt = (const float*)d_in[1];
    const float* A  = (const float*)d_in[2];
    const float* B  = (const float*)d_in[3];
    const float* bA = (const float*)d_in[4];
    const float* W1 = (const float*)d_in[5];
    const float* b1 = (const float*)d_in[6];
    const float* W2 = (const float*)d_in[7];
    const float* b2 = (const float*)d_in[8];
    float* out = (float*)d_out;

    prep_kernel<<<SEQ / 256, 256>>>(u, B, bA);
    init_kernel<<<(CHUNKS + 256) / 256, 256>>>();

    // 6 full-Newton iterations: fresh Jacobian every sweep, exact linear
    // solve via affine scan every compose.
    int cur = 0;
    for (int it = 0; it < 6; it++) {
        sweep_kernel<<<CHUNKS / 32, 32>>>(A, dt, 0, cur);
        compose_scan_kernel<<<1, SCANT>>>(cur, cur ^ 1);
        cur ^= 1;
    }
    // Final: store all states with converged chunk starts
    sweep_kernel<<<CHUNKS / 32, 32>>>(A, dt, 2, cur);

    mlp_kernel<<<SEQ / 4 / 128, 128>>>(W1, b1, W2, b2, out);
}

// round 9
// speedup vs baseline: 180.7801x; 1.3950x over previous
#include <cuda_runtime.h>

#define SEQ    262144
#define HID    256
#define CHUNKS 4096
#define CLEN   64           // SEQ / CHUNKS
#define NBLK   32           // scan blocks
#define BT     128          // chunks per scan block = CHUNKS/NBLK

// Scratch (static — no allocs allowed)
__device__ float4 g_cT[SEQ];   // K*(B u_t + bA), interleaved [tw][chunk]
__device__ float4 g_xT[SEQ];   // membrane states, interleaved [tw][chunk]

// Affine map f(x) = M x + v; row i = (Mi0, Mi1, Mi2, vi)
struct Aff { float4 r0, r1, r2; };

__device__ Aff    g_f[CHUNKS];   // per-chunk linearized map (from sweep)
__device__ Aff    g_P[CHUNKS];   // local inclusive prefix maps (from C1)
__device__ float4 g_E[NBLK];     // exclusive block-entry state vectors (from C2)

__device__ __forceinline__ float ex2f(float x) {
    float y; asm("ex2.approx.f32 %0, %1;" : "=f"(y) : "f"(x)); return y;
}
__device__ __forceinline__ float rcpf(float x) {
    float y; asm("rcp.approx.f32 %0, %1;" : "=f"(y) : "f"(x)); return y;
}

// out = A ∘ B (apply B first): M' = A.M*B.M, v' = A.M*B.v + A.v
__device__ __forceinline__ Aff comp(const Aff& A, const Aff& B) {
    Aff o;
    o.r0.x = fmaf(A.r0.x, B.r0.x, fmaf(A.r0.y, B.r1.x, A.r0.z * B.r2.x));
    o.r0.y = fmaf(A.r0.x, B.r0.y, fmaf(A.r0.y, B.r1.y, A.r0.z * B.r2.y));
    o.r0.z = fmaf(A.r0.x, B.r0.z, fmaf(A.r0.y, B.r1.z, A.r0.z * B.r2.z));
    o.r0.w = fmaf(A.r0.x, B.r0.w, fmaf(A.r0.y, B.r1.w, fmaf(A.r0.z, B.r2.w, A.r0.w)));
    o.r1.x = fmaf(A.r1.x, B.r0.x, fmaf(A.r1.y, B.r1.x, A.r1.z * B.r2.x));
    o.r1.y = fmaf(A.r1.x, B.r0.y, fmaf(A.r1.y, B.r1.y, A.r1.z * B.r2.y));
    o.r1.z = fmaf(A.r1.x, B.r0.z, fmaf(A.r1.y, B.r1.z, A.r1.z * B.r2.z));
    o.r1.w = fmaf(A.r1.x, B.r0.w, fmaf(A.r1.y, B.r1.w, fmaf(A.r1.z, B.r2.w, A.r1.w)));
    o.r2.x = fmaf(A.r2.x, B.r0.x, fmaf(A.r2.y, B.r1.x, A.r2.z * B.r2.x));
    o.r2.y = fmaf(A.r2.x, B.r0.y, fmaf(A.r2.y, B.r1.y, A.r2.z * B.r2.y));
    o.r2.z = fmaf(A.r2.x, B.r0.z, fmaf(A.r2.y, B.r1.z, A.r2.z * B.r2.z));
    o.r2.w = fmaf(A.r2.x, B.r0.w, fmaf(A.r2.y, B.r1.w, fmaf(A.r2.z, B.r2.w, A.r2.w)));
    return o;
}

// ---------------------------------------------------------------------------
// Kernel 1: c_t = K*(B u_t + bA) interleaved; also init g_P=identity, g_E=0.
// ---------------------------------------------------------------------------
__global__ void prep_kernel(const float* __restrict__ u,
                            const float* __restrict__ B,
                            const float* __restrict__ bA) {
    int t = blockIdx.x * blockDim.x + threadIdx.x;
    if (t < CHUNKS) {
        Aff I;
        I.r0 = make_float4(1.f, 0.f, 0.f, 0.f);
        I.r1 = make_float4(0.f, 1.f, 0.f, 0.f);
        I.r2 = make_float4(0.f, 0.f, 1.f, 0.f);
        g_P[t] = I;
    }
    if (t < NBLK) g_E[t] = make_float4(0.f, 0.f, 0.f, 0.f);
    if (t >= SEQ) return;
    const float K = 2.8853900817779268f;
    float u0 = u[t], u1 = u[SEQ + t], u2 = u[2 * SEQ + t];
    float c0 = K * fmaf(B[0], u0, fmaf(B[1], u1, fmaf(B[2], u2, bA[0])));
    float c1 = K * fmaf(B[3], u0, fmaf(B[4], u1, fmaf(B[5], u2, bA[1])));
    float c2 = K * fmaf(B[6], u0, fmaf(B[7], u1, fmaf(B[8], u2, bA[2])));
    int ch = t / CLEN, tw = t % CLEN;
    g_cT[tw * CHUNKS + ch] = make_float4(c0, c1, c2, 0.f);
}

// ---------------------------------------------------------------------------
// Kernel 2: parallel chunk sweep; reconstructs its own start from (P, E).
//   mode 0: integrate state + fresh 3x3 Jacobian -> writes g_f = (J, x_end - J s)
//   mode 2: integrate state only, store every x_t (final pass)
// ---------------------------------------------------------------------------
__global__ void sweep_kernel(const float* __restrict__ A,
                             const float* __restrict__ dtp, int mode) {
    int ch = blockIdx.x * blockDim.x + threadIdx.x;
    if (ch >= CHUNKS) return;
    const float K = 2.8853900817779268f;
    const float dt = dtp[0];
    const float a00 = A[0], a01 = A[1], a02 = A[2];
    const float a10 = A[3], a11 = A[4], a12 = A[5];
    const float a20 = A[6], a21 = A[7], a22 = A[8];
    const float k00 = K * a00, k01 = K * a01, k02 = K * a02;
    const float k10 = K * a10, k11 = K * a11, k12 = K * a12;
    const float k20 = K * a20, k21 = K * a21, k22 = K * a22;

    // start state: s = E_b for first chunk of block, else P[ch-1](E_b)
    int b = ch / BT, t = ch % BT;
    float4 E = g_E[b];
    float s0 = E.x, s1 = E.y, s2 = E.z;
    if (t > 0) {
        Aff P = g_P[ch - 1];
        float n0 = fmaf(P.r0.x, E.x, fmaf(P.r0.y, E.y, fmaf(P.r0.z, E.z, P.r0.w)));
        float n1 = fmaf(P.r1.x, E.x, fmaf(P.r1.y, E.y, fmaf(P.r1.z, E.z, P.r1.w)));
        float n2 = fmaf(P.r2.x, E.x, fmaf(P.r2.y, E.y, fmaf(P.r2.z, E.z, P.r2.w)));
        s0 = n0; s1 = n1; s2 = n2;
    }
    float x0 = s0, x1 = s1, x2 = s2;

    if (mode == 0) {
        float J00 = 1.f, J01 = 0.f, J02 = 0.f;
        float J10 = 0.f, J11 = 1.f, J12 = 0.f;
        float J20 = 0.f, J21 = 0.f, J22 = 1.f;
#pragma unroll 4
        for (int tw = 0; tw < CLEN; tw++) {
            float4 c = g_cT[tw * CHUNKS + ch];
            float w0 = fmaf(k00, x0, fmaf(k01, x1, fmaf(k02, x2, c.x)));
            float w1 = fmaf(k10, x0, fmaf(k11, x1, fmaf(k12, x2, c.y)));
            float w2 = fmaf(k20, x0, fmaf(k21, x1, fmaf(k22, x2, c.z)));
            float T0 = fmaf(-2.f, rcpf(ex2f(w0) + 1.f), 1.f);
            float T1 = fmaf(-2.f, rcpf(ex2f(w1) + 1.f), 1.f);
            float T2 = fmaf(-2.f, rcpf(ex2f(w2) + 1.f), 1.f);
            x0 = fmaf(dt, T0, x0);
            x1 = fmaf(dt, T1, x1);
            x2 = fmaf(dt, T2, x2);
            float d0 = dt * fmaf(-T0, T0, 1.f);
            float d1 = dt * fmaf(-T1, T1, 1.f);
            float d2 = dt * fmaf(-T2, T2, 1.f);
            float m00 = fmaf(a00, J00, fmaf(a01, J10, a02 * J20));
            float m01 = fmaf(a00, J01, fmaf(a01, J11, a02 * J21));
            float m02 = fmaf(a00, J02, fmaf(a01, J12, a02 * J22));
            float m10 = fmaf(a10, J00, fmaf(a11, J10, a12 * J20));
            float m11 = fmaf(a10, J01, fmaf(a11, J11, a12 * J21));
            float m12 = fmaf(a10, J02, fmaf(a11, J12, a12 * J22));
            float m20 = fmaf(a20, J00, fmaf(a21, J10, a22 * J20));
            float m21 = fmaf(a20, J01, fmaf(a21, J11, a22 * J21));
            float m22 = fmaf(a20, J02, fmaf(a21, J12, a22 * J22));
            J00 = fmaf(d0, m00, J00); J01 = fmaf(d0, m01, J01); J02 = fmaf(d0, m02, J02);
            J10 = fmaf(d1, m10, J10); J11 = fmaf(d1, m11, J11); J12 = fmaf(d1, m12, J12);
            J20 = fmaf(d2, m20, J20); J21 = fmaf(d2, m21, J21); J22 = fmaf(d2, m22, J22);
        }
        Aff f;
        f.r0 = make_float4(J00, J01, J02,
                           x0 - fmaf(J00, s0, fmaf(J01, s1, J02 * s2)));
        f.r1 = make_float4(J10, J11, J12,
                           x1 - fmaf(J10, s0, fmaf(J11, s1, J12 * s2)));
        f.r2 = make_float4(J20, J21, J22,
                           x2 - fmaf(J20, s0, fmaf(J21, s1, J22 * s2)));
        g_f[ch] = f;
    } else {
#pragma unroll 8
        for (int tw = 0; tw < CLEN; tw++) {
            float4 c = g_cT[tw * CHUNKS + ch];
            float w0 = fmaf(k00, x0, fmaf(k01, x1, fmaf(k02, x2, c.x)));
            float w1 = fmaf(k10, x0, fmaf(k11, x1, fmaf(k12, x2, c.y)));
            float w2 = fmaf(k20, x0, fmaf(k21, x1, fmaf(k22, x2, c.z)));
            float T0 = fmaf(-2.f, rcpf(ex2f(w0) + 1.f), 1.f);
            float T1 = fmaf(-2.f, rcpf(ex2f(w1) + 1.f), 1.f);
            float T2 = fmaf(-2.f, rcpf(ex2f(w2) + 1.f), 1.f);
            x0 = fmaf(dt, T0, x0);
            x1 = fmaf(dt, T1, x1);
            x2 = fmaf(dt, T2, x2);
            g_xT[tw * CHUNKS + ch] = make_float4(x0, x1, x2, 0.f);
        }
    }
}

// ---------------------------------------------------------------------------
// Kernel 3a (C1): per-block local scan of 128 maps -> g_P.  32 blocks on 32 SMs.
// ---------------------------------------------------------------------------
__global__ void scan_local_kernel() {
    __shared__ float4 s0[BT], s1[BT], s2[BT];
    int t = threadIdx.x;
    int c = blockIdx.x * BT + t;

    Aff G = g_f[c];
    s0[t] = G.r0; s1[t] = G.r1; s2[t] = G.r2;
    __syncthreads();

#pragma unroll
    for (int off = 1; off < BT; off <<= 1) {
        Aff P;
        bool act = (t >= off);
        if (act) { P.r0 = s0[t - off]; P.r1 = s1[t - off]; P.r2 = s2[t - off]; }
        __syncthreads();
        if (act) {
            G = comp(G, P);
            s0[t] = G.r0; s1[t] = G.r1; s2[t] = G.r2;
        }
        __syncthreads();
    }
    g_P[c] = G;
}

// ---------------------------------------------------------------------------
// Kernel 3b (C2): scan the 32 block totals -> exclusive entry vectors g_E.
// ---------------------------------------------------------------------------
__global__ void scan_block_kernel() {
    __shared__ float4 s0[NBLK], s1[NBLK], s2[NBLK];
    int t = threadIdx.x;

    Aff G = g_P[t * BT + (BT - 1)];   // block total
    s0[t] = G.r0; s1[t] = G.r1; s2[t] = G.r2;
    __syncwarp();

#pragma unroll
    for (int off = 1; off < NBLK; off <<= 1) {
        Aff P;
        bool act = (t >= off);
        if (act) { P.r0 = s0[t - off]; P.r1 = s1[t - off]; P.r2 = s2[t - off]; }
        __syncwarp();
        if (act) {
            G = comp(G, P);
            s0[t] = G.r0; s1[t] = G.r1; s2[t] = G.r2;
        }
        __syncwarp();
    }

    // exclusive entry state for block t: inclusive[t-1] applied to 0 = its v
    float4 E = make_float4(0.f, 0.f, 0.f, 0.f);
    if (t > 0) E = make_float4(s0[t - 1].w, s1[t - 1].w, s2[t - 1].w, 0.f);
    g_E[t] = E;
}

// ---------------------------------------------------------------------------
// Kernel 4: parallel MLP; reads interleaved states, writes planar out+membrane.
// ---------------------------------------------------------------------------
__global__ void mlp_kernel(const float* __restrict__ W1,
                           const float* __restrict__ b1,
                           const float* __restrict__ W2,
                           const float* __restrict__ b2,
                           float* __restrict__ out) {
    __shared__ float sW1[3 * HID];
    __shared__ float sW2[3 * HID];
    __shared__ float sb1[HID];
    __shared__ float sb2[4];

    for (int i = threadIdx.x; i < 3 * HID; i += blockDim.x) {
        sW1[i] = W1[i];
        sW2[i] = W2[i];
    }
    for (int i = threadIdx.x; i < HID; i += blockDim.x) sb1[i] = b1[i];
    if (threadIdx.x < 3) sb2[threadIdx.x] = b2[threadIdx.x];
    __syncthreads();

    int tid = blockIdx.x * blockDim.x + threadIdx.x;
    int t = tid * 4;
    if (t >= SEQ) return;
    int ch = t / CLEN, tw = t % CLEN;

    float xs0[4], xs1[4], xs2[4];
#pragma unroll
    for (int k = 0; k < 4; k++) {
        float4 v = g_xT[(tw + k) * CHUNKS + ch];
        xs0[k] = v.x; xs1[k] = v.y; xs2[k] = v.z;
    }

    float acc0[4], acc1[4], acc2[4];
#pragma unroll
    for (int k = 0; k < 4; k++) {
        acc0[k] = sb2[0]; acc1[k] = sb2[1]; acc2[k] = sb2[2];
    }

#pragma unroll 4
    for (int j = 0; j < HID; j++) {
        float w10 = sW1[3 * j], w11 = sW1[3 * j + 1], w12 = sW1[3 * j + 2];
        float bj = sb1[j];
        float q0 = sW2[j], q1 = sW2[HID + j], q2 = sW2[2 * HID + j];
#pragma unroll
        for (int k = 0; k < 4; k++) {
            float h = fmaf(w10, xs0[k], fmaf(w11, xs1[k], fmaf(w12, xs2[k], bj)));
            h = fmaxf(h, 0.f);
            acc0[k] = fmaf(q0, h, acc0[k]);
            acc1[k] = fmaf(q1, h, acc1[k]);
            acc2[k] = fmaf(q2, h, acc2[k]);
        }
    }

    float* mem = out + 3 * SEQ;
    *reinterpret_cast<float4*>(out + 0 * SEQ + t) = make_float4(acc0[0], acc0[1], acc0[2], acc0[3]);
    *reinterpret_cast<float4*>(out + 1 * SEQ + t) = make_float4(acc1[0], acc1[1], acc1[2], acc1[3]);
    *reinterpret_cast<float4*>(out + 2 * SEQ + t) = make_float4(acc2[0], acc2[1], acc2[2], acc2[3]);
    *reinterpret_cast<float4*>(mem + 0 * SEQ + t) = make_float4(xs0[0], xs0[1], xs0[2], xs0[3]);
    *reinterpret_cast<float4*>(mem + 1 * SEQ + t) = make_float4(xs1[0], xs1[1], xs1[2], xs1[3]);
    *reinterpret_cast<float4*>(mem + 2 * SEQ + t) = make_float4(xs2[0], xs2[1], xs2[2], xs2[3]);
}

// ---------------------------------------------------------------------------
extern "C" void kernel_launch(void* const* d_in, const int* in_sizes, int n_in,
                              void* d_out, int out_size) {
    const float* u  = (const float*)d_in[0];
    const float* dt = (const float*)d_in[1];
    const float* A  = (const float*)d_in[2];
    const float* B  = (const float*)d_in[3];
    const float* bA = (const float*)d_in[4];
    const float* W1 = (const float*)d_in[5];
    const float* b1 = (const float*)d_in[6];
    const float* W2 = (const float*)d_in[7];
    const float* b2 = (const float*)d_in[8];
    float* out = (float*)d_out;

    prep_kernel<<<SEQ / 256, 256>>>(u, B, bA);

    // 6 full-Newton iterations: sweep (start from P,E; fresh J; emit map)
    // -> local scan (32 SMs) -> block-total scan (1 warp).
    for (int it = 0; it < 6; it++) {
        sweep_kernel<<<CHUNKS / 32, 32>>>(A, dt, 0);
        scan_local_kernel<<<NBLK, BT>>>();
        scan_block_kernel<<<1, NBLK>>>();
    }
    // Final: store all states using converged (P, E)
    sweep_kernel<<<CHUNKS / 32, 32>>>(A, dt, 2);

    mlp_kernel<<<SEQ / 4 / 128, 128>>>(W1, b1, W2, b2, out);
}